// round 14
// baseline (speedup 1.0000x reference)
#include <cuda_runtime.h>
#include <cuda_bf16.h>
#include <cuda_fp16.h>
#include <cuda_pipeline.h>
#include <mma.h>
#include <math.h>
#include <stdint.h>

using namespace nvcuda;

// Problem constants
#define BB 128
#define SS 256
#define EE 825
#define KP 832            // E padded; col 825 = constant 1 (bias trick)
#define HH 600
#define HHP 608
#define G4 2400
#define G4P 2432
#define MROWS 32768
#define CTX_STRIDE 1200
#define OUT_BLK 153600
#define NIH 4800
#define NIH_PAD 4864
#define NHW_PAD 896

// ---------------------------------------------------------------------------
// Scratch (device globals)
// ---------------------------------------------------------------------------
__device__ float g_gates[(size_t)MROWS * NIH_PAD];   // gates out; also highway raw scratch
__device__ __half g_A1[(size_t)MROWS * KP];          // activations fp16 (ping)
__device__ __half g_A2[(size_t)MROWS * KP];          // activations fp16 (pong)
__device__ __half g_B[(size_t)NIH_PAD * KP];         // weights fp16 (bias in col 825)
__device__ __nv_bfloat16 g_Whi[2 * G4P * HHP];       // recurrence weights split bf16
__device__ __nv_bfloat16 g_Wlo[2 * G4P * HHP];
__device__ __nv_bfloat16 g_hbf_hi[2][2 * BB * HHP];
__device__ __nv_bfloat16 g_hbf_lo[2][2 * BB * HHP];
__device__ float g_h[2 * BB * HH];
__device__ float g_c[2 * BB * HH];

__device__ __forceinline__ float sigm(float x) { return 1.0f / (1.0f + expf(-x)); }

// ---------------------------------------------------------------------------
// Big GEMM: C = A @ B^T, pure fp16, fp32 accum.
// 128x128 CTA tile, 8 warps (wm 0..3 x wn 0..1), warp 32x64.
// Stage = 2 mats x 128 rows x 80B = 20480B; 3-stage cp.async ring.
// ---------------------------------------------------------------------------
#define STG 20480

__global__ void __launch_bounds__(256) gemm_fp16_kernel(
        const __half* __restrict__ A, const __half* __restrict__ B,
        float* __restrict__ C, int ldc) {
    extern __shared__ char dsm[];
    const int tid = threadIdx.x;
    const int wid = tid >> 5;
    const int wm = wid >> 1;        // 0..3
    const int wn = wid & 1;         // 0..1
    const size_t m0 = (size_t)blockIdx.x * 128;
    const size_t n0 = (size_t)blockIdx.y * 128;
    const int NKB = KP / 32;        // 26

    const __half* gA = A + m0 * KP;
    const __half* gB = B + n0 * KP;

    wmma::fragment<wmma::accumulator, 16, 16, 16, float> acc[2][4];
    #pragma unroll
    for (int i = 0; i < 2; i++)
        #pragma unroll
        for (int j = 0; j < 4; j++)
            wmma::fill_fragment(acc[i][j], 0.0f);

    auto stage_fill = [&](int stg, int ko) {
        char* st = dsm + stg * STG;
        #pragma unroll
        for (int r = 0; r < 4; r++) {
            int idx = tid + r * 256;        // 0..1023
            int arr = idx >> 9;             // 0..1
            int rem = idx & 511;
            int row = rem >> 2, seg = rem & 3;
            const __half* src = (arr ? gB : gA) + (size_t)row * KP + ko + seg * 8;
            __pipeline_memcpy_async(st + arr * 10240 + row * 80 + seg * 16, src, 16);
        }
        __pipeline_commit();
    };

    stage_fill(0, 0);
    stage_fill(1, 32);

    int stg = 0;
    for (int kb = 0; kb < NKB; kb++) {
        __pipeline_wait_prior(1);
        __syncthreads();
        if (kb + 2 < NKB)
            stage_fill((stg + 2) % 3, (kb + 2) * 32);

        char* st = dsm + stg * STG;
        typedef __half (*T40)[40];
        T40 sA = (T40)st;
        T40 sB = (T40)(st + 10240);

        #pragma unroll
        for (int ks = 0; ks < 2; ks++) {
            wmma::fragment<wmma::matrix_a, 16, 16, 16, __half, wmma::row_major> a[2];
            wmma::fragment<wmma::matrix_b, 16, 16, 16, __half, wmma::col_major> b[4];
            #pragma unroll
            for (int i = 0; i < 2; i++)
                wmma::load_matrix_sync(a[i], &sA[wm * 32 + i * 16][ks * 16], 40);
            #pragma unroll
            for (int j = 0; j < 4; j++)
                wmma::load_matrix_sync(b[j], &sB[wn * 64 + j * 16][ks * 16], 40);
            #pragma unroll
            for (int i = 0; i < 2; i++)
                #pragma unroll
                for (int j = 0; j < 4; j++)
                    wmma::mma_sync(acc[i][j], a[i], b[j], acc[i][j]);
        }
        stg = (stg + 1) % 3;
    }

    #pragma unroll
    for (int i = 0; i < 2; i++)
        #pragma unroll
        for (int j = 0; j < 4; j++)
            wmma::store_matrix_sync(&C[(m0 + wm * 32 + i * 16) * ldc + n0 + wn * 64 + j * 16],
                                    acc[i][j], ldc, wmma::mem_row_major);
}

// ---------------------------------------------------------------------------
// Fused recurrent step, WIDE tile: gate-quad GEMM + LSTM cell.
// grid (2, 38, 2) = (m-tile of 64, hh-tile of 16, dir) = 152 CTAs.
// CTA computes 64 rows x 64 gate-cols (i,f,g,o x 16 hh), K=HHP, split bf16
// 3-product, then applies the cell and writes c, h, split-h ping-pong, ctx.
// hh tiles cover padded 608; hh >= 600 lanes compute discarded values
// (their W rows alias the next gate's rows) and are guarded at the cell.
// 4 warps, warp = 16 rows x 64 cols (acc[4]).
// Stage = A hi/lo (64x40 each) + B hi/lo (64x40 each) = 20480B; 2 stages.
// ---------------------------------------------------------------------------
#define SSTG 20480

__global__ void __launch_bounds__(128) step_fused_kernel(float* __restrict__ context, int t) {
    __shared__ char sm[2 * SSTG];
    const int tid = threadIdx.x;
    const int wid = tid >> 5;             // 0..3 : 16-row slice
    const int mt = blockIdx.x;            // 0..1
    const int hh0 = blockIdx.y * 16;      // 0..592
    const int d = blockIdx.z;
    const int cur = t & 1, nxt = cur ^ 1;

    const __nv_bfloat16* Ahi = g_hbf_hi[cur] + (size_t)(d * BB + mt * 64) * HHP;
    const __nv_bfloat16* Alo = g_hbf_lo[cur] + (size_t)(d * BB + mt * 64) * HHP;
    const __nv_bfloat16* Whi = g_Whi + (size_t)d * G4P * HHP;
    const __nv_bfloat16* Wlo = g_Wlo + (size_t)d * G4P * HHP;

    // per-thread staging coordinates: tasks idx = tid and tid+128 -> rows tid>>2 and 32+(tid>>2)
    const int seg = tid & 3;
    const int r0 = tid >> 2;              // 0..31
    const int r1 = r0 + 32;               // 32..63
    const size_t asrc0 = (size_t)r0 * HHP + seg * 8;
    const size_t asrc1 = (size_t)r1 * HHP + seg * 8;
    const size_t bsrc0 = (size_t)((r0 >> 4) * HH + hh0 + (r0 & 15)) * HHP + seg * 8;
    const size_t bsrc1 = (size_t)((r1 >> 4) * HH + hh0 + (r1 & 15)) * HHP + seg * 8;

    wmma::fragment<wmma::accumulator, 16, 16, 16, float> acc[4];
    #pragma unroll
    for (int j = 0; j < 4; j++) wmma::fill_fragment(acc[j], 0.0f);

    const int NKB = HHP / 32;             // 19

    auto stage_fill = [&](char* st, int ko) {
        __pipeline_memcpy_async(st + r0 * 80 + seg * 16,         Ahi + asrc0 + ko, 16);
        __pipeline_memcpy_async(st + r1 * 80 + seg * 16,         Ahi + asrc1 + ko, 16);
        __pipeline_memcpy_async(st + 5120 + r0 * 80 + seg * 16,  Alo + asrc0 + ko, 16);
        __pipeline_memcpy_async(st + 5120 + r1 * 80 + seg * 16,  Alo + asrc1 + ko, 16);
        __pipeline_memcpy_async(st + 10240 + r0 * 80 + seg * 16, Whi + bsrc0 + ko, 16);
        __pipeline_memcpy_async(st + 10240 + r1 * 80 + seg * 16, Whi + bsrc1 + ko, 16);
        __pipeline_memcpy_async(st + 15360 + r0 * 80 + seg * 16, Wlo + bsrc0 + ko, 16);
        __pipeline_memcpy_async(st + 15360 + r1 * 80 + seg * 16, Wlo + bsrc1 + ko, 16);
        __pipeline_commit();
    };

    stage_fill(sm, 0);

    for (int kb = 0; kb < NKB; kb++) {
        __pipeline_wait_prior(0);
        __syncthreads();
        if (kb + 1 < NKB)
            stage_fill(sm + ((kb + 1) & 1) * SSTG, (kb + 1) * 32);

        char* st = sm + (kb & 1) * SSTG;
        typedef __nv_bfloat16 (*T40)[40];
        T40 sAh = (T40)st;
        T40 sAl = (T40)(st + 5120);
        T40 sBh = (T40)(st + 10240);
        T40 sBl = (T40)(st + 15360);

        #pragma unroll
        for (int ks = 0; ks < 2; ks++) {
            wmma::fragment<wmma::matrix_a, 16, 16, 16, __nv_bfloat16, wmma::row_major> ah, al;
            wmma::fragment<wmma::matrix_b, 16, 16, 16, __nv_bfloat16, wmma::col_major> bh[4], bl[4];
            wmma::load_matrix_sync(ah, &sAh[wid * 16][ks * 16], 40);
            wmma::load_matrix_sync(al, &sAl[wid * 16][ks * 16], 40);
            #pragma unroll
            for (int j = 0; j < 4; j++) {
                wmma::load_matrix_sync(bh[j], &sBh[j * 16][ks * 16], 40);
                wmma::load_matrix_sync(bl[j], &sBl[j * 16][ks * 16], 40);
            }
            #pragma unroll
            for (int j = 0; j < 4; j++) {
                wmma::mma_sync(acc[j], ah, bh[j], acc[j]);
                wmma::mma_sync(acc[j], ah, bl[j], acc[j]);
                wmma::mma_sync(acc[j], al, bh[j], acc[j]);
            }
        }
        __syncthreads();
    }

    // gates through smem (stage area; GEMM done): 64 rows x 64 cols f32 = 16KB
    float (*sg)[64] = (float(*)[64])sm;
    #pragma unroll
    for (int j = 0; j < 4; j++)
        wmma::store_matrix_sync(&sg[wid * 16][j * 16], acc[j], 64, wmma::mem_row_major);
    __syncthreads();

    // LSTM cell: 64 rows x 16 hh = 1024 elements (hh >= 600 guarded out)
    #pragma unroll
    for (int q = 0; q < 8; q++) {
        int e = tid + q * 128;
        int bl_ = e >> 4, hl = e & 15;
        int hh = hh0 + hl;
        if (hh >= HH) continue;
        int b = mt * 64 + bl_;
        size_t gx = ((size_t)b * SS + t) * NIH_PAD + d * G4;
        float gi = sg[bl_][hl]      + g_gates[gx + hh];
        float gf = sg[bl_][16 + hl] + g_gates[gx + HH + hh];
        float gg = sg[bl_][32 + hl] + g_gates[gx + 2 * HH + hh];
        float go = sg[bl_][48 + hl] + g_gates[gx + 3 * HH + hh];
        size_t ci = (size_t)(d * BB + b) * HH + hh;
        float cold = g_c[ci];
        float cn = sigm(gf) * cold + sigm(gi) * tanhf(gg);
        float hn = sigm(go) * tanhf(cn);
        g_c[ci] = cn;
        g_h[ci] = hn;
        size_t hb = (size_t)(d * BB + b) * HHP + hh;
        __nv_bfloat16 hi = __float2bfloat16(hn);
        g_hbf_hi[nxt][hb] = hi;
        g_hbf_lo[nxt][hb] = __float2bfloat16(hn - __bfloat162float(hi));
        context[(size_t)t * OUT_BLK + (size_t)b * CTX_STRIDE + d * HH + hh] = hn;
    }
}

// ---------------------------------------------------------------------------
// Conversions / elementwise
// ---------------------------------------------------------------------------
__global__ void init_kernel(const float* __restrict__ h0, const float* __restrict__ c0) {
    int idx = blockIdx.x * blockDim.x + threadIdx.x;
    if (idx < 2 * BB * HH) { g_h[idx] = h0[idx]; g_c[idx] = c0[idx]; }
    if (idx < 2 * BB * HHP) {
        int hh = idx % HHP;
        int db = idx / HHP;
        float v = (hh < HH) ? h0[db * HH + hh] : 0.0f;
        __nv_bfloat16 hi = __float2bfloat16(v);
        __nv_bfloat16 lo = __float2bfloat16(v - __bfloat162float(hi));
        g_hbf_hi[0][idx] = hi; g_hbf_lo[0][idx] = lo;
        g_hbf_hi[1][idx] = hi; g_hbf_lo[1][idx] = lo;
    }
}

// x -> fp16, col 825 = 1.0 (bias column), cols > 825 = 0
__global__ void convA_kernel(const float* __restrict__ src) {
    int idx = blockIdx.x * blockDim.x + threadIdx.x;
    if (idx >= MROWS * KP) return;
    int col = idx % KP, row = idx / KP;
    float v;
    if (col < EE)       v = src[(size_t)row * EE + col];
    else if (col == EE) v = 1.0f;
    else                v = 0.0f;
    g_A1[idx] = __float2half(v);
}

// 3 highway weight mats (layer l) -> g_B fp16, bias at col 825
__global__ void convW3_kernel(const float* __restrict__ Wg, const float* __restrict__ bg,
                              const float* __restrict__ Wn, const float* __restrict__ bn,
                              const float* __restrict__ Wl, const float* __restrict__ bl) {
    int idx = blockIdx.x * blockDim.x + threadIdx.x;
    if (idx >= 3 * NHW_PAD * KP) return;
    int col = idx % KP;
    int rowm = idx / KP;
    int row = rowm % NHW_PAD;
    int mat = rowm / NHW_PAD;
    const float* W = (mat == 0) ? Wg : (mat == 1) ? Wn : Wl;
    const float* bs = (mat == 0) ? bg : (mat == 1) ? bn : bl;
    float v = 0.0f;
    if (row < EE) {
        if (col < EE)       v = W[(size_t)row * EE + col];
        else if (col == EE) v = bs[row];
    }
    g_B[idx] = __float2half(v);
}

// W_ih -> g_B fp16, (b_ih + b_hh) at col 825
__global__ void convWih_kernel(const float* __restrict__ W,
                               const float* __restrict__ b1, const float* __restrict__ b2) {
    int idx = blockIdx.x * blockDim.x + threadIdx.x;
    if (idx >= NIH_PAD * KP) return;
    int col = idx % KP, row = idx / KP;
    float v = 0.0f;
    if (row < NIH) {
        if (col < EE)       v = W[(size_t)row * EE + col];
        else if (col == EE) v = b1[row] + b2[row];
    }
    g_B[idx] = __float2half(v);
}

__global__ void convWhh_kernel(const float* __restrict__ W) {
    int idx = blockIdx.x * blockDim.x + threadIdx.x;
    if (idx >= 2 * G4P * HHP) return;
    int col = idx % HHP;
    int rowd = idx / HHP;
    int row = rowd % G4P;
    int d = rowd / G4P;
    float v = (row < G4 && col < HH) ? W[((size_t)d * G4 + row) * HH + col] : 0.0f;
    __nv_bfloat16 hi = __float2bfloat16(v);
    g_Whi[idx] = hi;
    g_Wlo[idx] = __float2bfloat16(v - __bfloat162float(hi));
}

// highway combine: raw G/N/L pre-biased; y -> fp16 out (ping-pong)
__global__ void combine_kernel(const float* __restrict__ rawG, const float* __restrict__ rawN,
                               const float* __restrict__ rawL,
                               __half* __restrict__ Aout) {
    int idx = blockIdx.x * blockDim.x + threadIdx.x;
    if (idx >= MROWS * KP) return;
    int col = idx % KP, row = idx / KP;
    float y;
    if (col < EE) {
        size_t r = (size_t)row * NHW_PAD + col;
        float gate = sigm(rawG[r]);
        float nl   = fmaxf(rawN[r], 0.0f);
        float ln   = rawL[r];
        y = gate * nl + (1.0f - gate) * ln;
    } else if (col == EE) y = 1.0f;
    else y = 0.0f;
    Aout[idx] = __float2half(y);
}

__global__ void finalize_kernel(float* __restrict__ out) {
    int idx = blockIdx.x * blockDim.x + threadIdx.x;
    if (idx >= OUT_BLK) return;
    const float* ctx_last = out + 4L * OUT_BLK + (long)(SS - 1) * OUT_BLK;
    float v = ctx_last[idx];
    out[idx] = v;
    out[OUT_BLK + idx] = v;
    out[2L * OUT_BLK + idx] = g_h[idx];
    out[3L * OUT_BLK + idx] = g_c[idx];
}

// ---------------------------------------------------------------------------
extern "C" void kernel_launch(void* const* d_in, const int* in_sizes, int n_in,
                              void* d_out, int out_size) {
    const float* x      = (const float*)d_in[0];
    const float* h0     = (const float*)d_in[1];
    const float* c0     = (const float*)d_in[2];
    const float* hw_Wg  = (const float*)d_in[3];
    const float* hw_bg  = (const float*)d_in[4];
    const float* hw_Wn  = (const float*)d_in[5];
    const float* hw_bn  = (const float*)d_in[6];
    const float* hw_Wl  = (const float*)d_in[7];
    const float* hw_bl  = (const float*)d_in[8];
    const float* W_ih   = (const float*)d_in[9];
    const float* W_hh   = (const float*)d_in[10];
    const float* b_ih   = (const float*)d_in[11];
    const float* b_hh   = (const float*)d_in[12];
    float* out = (float*)d_out;

    static bool attr_set = false;
    if (!attr_set) {
        cudaFuncSetAttribute(gemm_fp16_kernel,
                             cudaFuncAttributeMaxDynamicSharedMemorySize, 3 * STG);
        attr_set = true;
    }

    float *p_gates;
    __half *p_A1, *p_A2, *p_B;
    cudaGetSymbolAddress((void**)&p_gates, g_gates);
    cudaGetSymbolAddress((void**)&p_A1, g_A1);
    cudaGetSymbolAddress((void**)&p_A2, g_A2);
    cudaGetSymbolAddress((void**)&p_B, g_B);

    init_kernel<<<(2 * BB * HHP + 255) / 256, 256>>>(h0, c0);
    convWhh_kernel<<<(2 * G4P * HHP + 255) / 256, 256>>>(W_hh);
    convA_kernel<<<(MROWS * KP + 255) / 256, 256>>>(x);

    // Highway: 2 layers, 3 separate GEMMs + combine (pure fp16)
    float* raw[3] = { p_gates,
                      p_gates + (size_t)MROWS * NHW_PAD,
                      p_gates + 2 * (size_t)MROWS * NHW_PAD };
    dim3 gHW(MROWS / 128, NHW_PAD / 128);  // 256 x 7
    for (int l = 0; l < 2; l++) {
        convW3_kernel<<<(3 * NHW_PAD * KP + 255) / 256, 256>>>(
            hw_Wg + (size_t)l * EE * EE, hw_bg + l * EE,
            hw_Wn + (size_t)l * EE * EE, hw_bn + l * EE,
            hw_Wl + (size_t)l * EE * EE, hw_bl + l * EE);
        const __half* A = (l == 0) ? p_A1 : p_A2;
        for (int w = 0; w < 3; w++)
            gemm_fp16_kernel<<<gHW, 256, 3 * STG>>>(A,
                p_B + (size_t)w * NHW_PAD * KP, raw[w], NHW_PAD);
        combine_kernel<<<(MROWS * KP + 255) / 256, 256>>>(
            raw[0], raw[1], raw[2], (l == 0) ? p_A2 : p_A1);
    }

    // Input-gate precompute (bias folded via col 825)
    convWih_kernel<<<(NIH_PAD * KP + 255) / 256, 256>>>(W_ih, b_ih, b_hh);
    dim3 gGX(MROWS / 128, NIH_PAD / 128);  // 256 x 38
    gemm_fp16_kernel<<<gGX, 256, 3 * STG>>>(p_A1, p_B, p_gates, NIH_PAD);

    // Sequential recurrence: one fused wide-tile kernel per step
    dim3 gST(2, HHP / 16, 2);  // (m-tile, hh-tile of 16, dir) = 152 CTAs
    float* context = out + 4L * OUT_BLK;
    for (int t = 0; t < SS; t++) {
        step_fused_kernel<<<gST, 128>>>(context, t);
    }

    finalize_kernel<<<(OUT_BLK + 255) / 256, 256>>>(out);
}

// round 15
// speedup vs baseline: 1.2098x; 1.2098x over previous
#include <cuda_runtime.h>
#include <cuda_bf16.h>
#include <cuda_fp16.h>
#include <cuda_pipeline.h>
#include <mma.h>
#include <math.h>
#include <stdint.h>

using namespace nvcuda;

// Problem constants
#define BB 128
#define SS 256
#define EE 825
#define KP 832            // E padded; col 825 = constant 1 (bias trick)
#define HH 600
#define HHP 640           // H padded to 10*64 (zero padding)
#define G4 2400
#define G4P 2432
#define MROWS 32768
#define CTX_STRIDE 1200
#define OUT_BLK 153600
#define NIH 4800
#define NIH_PAD 4864
#define NHW_PAD 896

// ---------------------------------------------------------------------------
// Scratch (device globals)
// ---------------------------------------------------------------------------
__device__ float g_gates[(size_t)MROWS * NIH_PAD];   // gates out; also highway raw scratch
__device__ __half g_A1[(size_t)MROWS * KP];          // activations fp16 (ping)
__device__ __half g_A2[(size_t)MROWS * KP];          // activations fp16 (pong)
__device__ __half g_B[(size_t)NIH_PAD * KP];         // weights fp16 (bias in col 825)
__device__ __nv_bfloat16 g_Whi[2 * G4P * HHP];       // recurrence weights split bf16
__device__ __nv_bfloat16 g_Wlo[2 * G4P * HHP];
__device__ __nv_bfloat16 g_hbf_hi[2][2 * BB * HHP];
__device__ __nv_bfloat16 g_hbf_lo[2][2 * BB * HHP];
__device__ float g_h[2 * BB * HH];
__device__ float g_c[2 * BB * HH];

__device__ __forceinline__ float sigm(float x) { return 1.0f / (1.0f + expf(-x)); }

// ---------------------------------------------------------------------------
// Big GEMM: C = A @ B^T, pure fp16, fp32 accum.
// 128x128 CTA tile, 8 warps (wm 0..3 x wn 0..1), warp 32x64.
// Stage = 2 mats x 128 rows x 80B = 20480B; 3-stage cp.async ring.
// ---------------------------------------------------------------------------
#define STG 20480

__global__ void __launch_bounds__(256) gemm_fp16_kernel(
        const __half* __restrict__ A, const __half* __restrict__ B,
        float* __restrict__ C, int ldc) {
    extern __shared__ char dsm[];
    const int tid = threadIdx.x;
    const int wid = tid >> 5;
    const int wm = wid >> 1;        // 0..3
    const int wn = wid & 1;         // 0..1
    const size_t m0 = (size_t)blockIdx.x * 128;
    const size_t n0 = (size_t)blockIdx.y * 128;
    const int NKB = KP / 32;        // 26

    const __half* gA = A + m0 * KP;
    const __half* gB = B + n0 * KP;

    wmma::fragment<wmma::accumulator, 16, 16, 16, float> acc[2][4];
    #pragma unroll
    for (int i = 0; i < 2; i++)
        #pragma unroll
        for (int j = 0; j < 4; j++)
            wmma::fill_fragment(acc[i][j], 0.0f);

    auto stage_fill = [&](int stg, int ko) {
        char* st = dsm + stg * STG;
        #pragma unroll
        for (int r = 0; r < 4; r++) {
            int idx = tid + r * 256;        // 0..1023
            int arr = idx >> 9;             // 0..1
            int rem = idx & 511;
            int row = rem >> 2, seg = rem & 3;
            const __half* src = (arr ? gB : gA) + (size_t)row * KP + ko + seg * 8;
            __pipeline_memcpy_async(st + arr * 10240 + row * 80 + seg * 16, src, 16);
        }
        __pipeline_commit();
    };

    stage_fill(0, 0);
    stage_fill(1, 32);

    int stg = 0;
    for (int kb = 0; kb < NKB; kb++) {
        __pipeline_wait_prior(1);
        __syncthreads();
        if (kb + 2 < NKB)
            stage_fill((stg + 2) % 3, (kb + 2) * 32);

        char* st = dsm + stg * STG;
        typedef __half (*T40)[40];
        T40 sA = (T40)st;
        T40 sB = (T40)(st + 10240);

        #pragma unroll
        for (int ks = 0; ks < 2; ks++) {
            wmma::fragment<wmma::matrix_a, 16, 16, 16, __half, wmma::row_major> a[2];
            wmma::fragment<wmma::matrix_b, 16, 16, 16, __half, wmma::col_major> b[4];
            #pragma unroll
            for (int i = 0; i < 2; i++)
                wmma::load_matrix_sync(a[i], &sA[wm * 32 + i * 16][ks * 16], 40);
            #pragma unroll
            for (int j = 0; j < 4; j++)
                wmma::load_matrix_sync(b[j], &sB[wn * 64 + j * 16][ks * 16], 40);
            #pragma unroll
            for (int i = 0; i < 2; i++)
                #pragma unroll
                for (int j = 0; j < 4; j++)
                    wmma::mma_sync(acc[i][j], a[i], b[j], acc[i][j]);
        }
        stg = (stg + 1) % 3;
    }

    #pragma unroll
    for (int i = 0; i < 2; i++)
        #pragma unroll
        for (int j = 0; j < 4; j++)
            wmma::store_matrix_sync(&C[(m0 + wm * 32 + i * 16) * ldc + n0 + wn * 64 + j * 16],
                                    acc[i][j], ldc, wmma::mem_row_major);
}

// ---------------------------------------------------------------------------
// Fused recurrent step (R10 tile shape, K-chunk 64): gate-quad GEMM + cell.
// grid (2, 75, 2) = 300 CTAs, 128 thr (4 warps), CTA tile 64 rows x 32 cols.
// K-loop: 10 chunks of 64 (HHP = 640, zero-padded) -> half the sync points.
// Stage layout (27648B): sAh[64][72] @0, sAl @9216, sBh[32][72] @18432,
// sBl @23040. 2 stages dynamic smem = 55296B.
// Math identical to R10 (same MMA sequence per output).
// ---------------------------------------------------------------------------
#define SSTG 27648

__global__ void __launch_bounds__(128) step_fused_kernel(float* __restrict__ context, int t) {
    extern __shared__ char sm[];
    const int tid = threadIdx.x;
    const int wid = tid >> 5;             // 0..3 : 16-row slice
    const int mt = blockIdx.x;            // 0..1
    const int hh0 = blockIdx.y * 8;       // 0..592
    const int d = blockIdx.z;
    const int cur = t & 1, nxt = cur ^ 1;

    const __nv_bfloat16* Ahi = g_hbf_hi[cur] + (size_t)(d * BB + mt * 64) * HHP;
    const __nv_bfloat16* Alo = g_hbf_lo[cur] + (size_t)(d * BB + mt * 64) * HHP;
    const __nv_bfloat16* Whi = g_Whi + (size_t)d * G4P * HHP;
    const __nv_bfloat16* Wlo = g_Wlo + (size_t)d * G4P * HHP;

    wmma::fragment<wmma::accumulator, 16, 16, 16, float> acc[2];
    wmma::fill_fragment(acc[0], 0.0f);
    wmma::fill_fragment(acc[1], 0.0f);

    const int NKB = HHP / 64;             // 10

    auto stage_fill = [&](char* st, int ko) {
        // A: 1024 tasks = hi/lo x 64 rows x 8 segs of 16B
        #pragma unroll
        for (int r = 0; r < 8; r++) {
            int idx = tid + r * 128;
            int hl = idx >> 9;
            int rem = idx & 511;
            int row = rem >> 3, seg = rem & 7;
            const __nv_bfloat16* src = (hl ? Alo : Ahi) + (size_t)row * HHP + ko + seg * 8;
            __pipeline_memcpy_async(st + hl * 9216 + row * 144 + seg * 16, src, 16);
        }
        // B: 512 tasks = hi/lo x 32 rows x 8 segs
        #pragma unroll
        for (int r = 0; r < 4; r++) {
            int idx = tid + r * 128;
            int hl = idx >> 8;
            int rem = idx & 255;
            int row = rem >> 3, seg = rem & 7;
            const __nv_bfloat16* src = (hl ? Wlo : Whi) +
                (size_t)((row >> 3) * HH + hh0 + (row & 7)) * HHP + ko + seg * 8;
            __pipeline_memcpy_async(st + 18432 + hl * 4608 + row * 144 + seg * 16, src, 16);
        }
        __pipeline_commit();
    };

    stage_fill(sm, 0);

    for (int kb = 0; kb < NKB; kb++) {
        __pipeline_wait_prior(0);
        __syncthreads();
        if (kb + 1 < NKB)
            stage_fill(sm + ((kb + 1) & 1) * SSTG, (kb + 1) * 64);

        char* st = sm + (kb & 1) * SSTG;
        typedef __nv_bfloat16 (*T72)[72];
        T72 sAh = (T72)st;
        T72 sAl = (T72)(st + 9216);
        T72 sBh = (T72)(st + 18432);
        T72 sBl = (T72)(st + 23040);

        #pragma unroll
        for (int ks = 0; ks < 4; ks++) {
            wmma::fragment<wmma::matrix_a, 16, 16, 16, __nv_bfloat16, wmma::row_major> ah, al;
            wmma::fragment<wmma::matrix_b, 16, 16, 16, __nv_bfloat16, wmma::col_major> bh[2], bl[2];
            wmma::load_matrix_sync(ah, &sAh[wid * 16][ks * 16], 72);
            wmma::load_matrix_sync(al, &sAl[wid * 16][ks * 16], 72);
            #pragma unroll
            for (int j = 0; j < 2; j++) {
                wmma::load_matrix_sync(bh[j], &sBh[j * 16][ks * 16], 72);
                wmma::load_matrix_sync(bl[j], &sBl[j * 16][ks * 16], 72);
            }
            #pragma unroll
            for (int j = 0; j < 2; j++) {
                wmma::mma_sync(acc[j], ah, bh[j], acc[j]);
                wmma::mma_sync(acc[j], ah, bl[j], acc[j]);
                wmma::mma_sync(acc[j], al, bh[j], acc[j]);
            }
        }
        __syncthreads();
    }

    // gates through smem (stage 0 alias; GEMM done): 64 x 32 f32 = 8KB
    float (*sg)[32] = (float(*)[32])sm;
    wmma::store_matrix_sync(&sg[wid * 16][0], acc[0], 32, wmma::mem_row_major);
    wmma::store_matrix_sync(&sg[wid * 16][16], acc[1], 32, wmma::mem_row_major);
    __syncthreads();

    // LSTM cell: 512 elements (64 rows x 8 hh)
    #pragma unroll
    for (int q = 0; q < 4; q++) {
        int e = tid + q * 128;
        int bl_ = e >> 3, hl = e & 7;
        int b = mt * 64 + bl_;
        int hh = hh0 + hl;
        size_t gx = ((size_t)b * SS + t) * NIH_PAD + d * G4;
        float gi = sg[bl_][hl]      + g_gates[gx + hh];
        float gf = sg[bl_][8 + hl]  + g_gates[gx + HH + hh];
        float gg = sg[bl_][16 + hl] + g_gates[gx + 2 * HH + hh];
        float go = sg[bl_][24 + hl] + g_gates[gx + 3 * HH + hh];
        size_t ci = (size_t)(d * BB + b) * HH + hh;
        float cold = g_c[ci];
        float cn = sigm(gf) * cold + sigm(gi) * tanhf(gg);
        float hn = sigm(go) * tanhf(cn);
        g_c[ci] = cn;
        g_h[ci] = hn;
        size_t hb = (size_t)(d * BB + b) * HHP + hh;
        __nv_bfloat16 hi = __float2bfloat16(hn);
        g_hbf_hi[nxt][hb] = hi;
        g_hbf_lo[nxt][hb] = __float2bfloat16(hn - __bfloat162float(hi));
        context[(size_t)t * OUT_BLK + (size_t)b * CTX_STRIDE + d * HH + hh] = hn;
    }
}

// ---------------------------------------------------------------------------
// Conversions / elementwise
// ---------------------------------------------------------------------------
__global__ void init_kernel(const float* __restrict__ h0, const float* __restrict__ c0) {
    int idx = blockIdx.x * blockDim.x + threadIdx.x;
    if (idx < 2 * BB * HH) { g_h[idx] = h0[idx]; g_c[idx] = c0[idx]; }
    if (idx < 2 * BB * HHP) {
        int hh = idx % HHP;
        int db = idx / HHP;
        float v = (hh < HH) ? h0[db * HH + hh] : 0.0f;
        __nv_bfloat16 hi = __float2bfloat16(v);
        __nv_bfloat16 lo = __float2bfloat16(v - __bfloat162float(hi));
        g_hbf_hi[0][idx] = hi; g_hbf_lo[0][idx] = lo;
        g_hbf_hi[1][idx] = hi; g_hbf_lo[1][idx] = lo;
    }
}

// x -> fp16, col 825 = 1.0 (bias column), cols > 825 = 0
__global__ void convA_kernel(const float* __restrict__ src) {
    int idx = blockIdx.x * blockDim.x + threadIdx.x;
    if (idx >= MROWS * KP) return;
    int col = idx % KP, row = idx / KP;
    float v;
    if (col < EE)       v = src[(size_t)row * EE + col];
    else if (col == EE) v = 1.0f;
    else                v = 0.0f;
    g_A1[idx] = __float2half(v);
}

// 3 highway weight mats (layer l) -> g_B fp16, bias at col 825
__global__ void convW3_kernel(const float* __restrict__ Wg, const float* __restrict__ bg,
                              const float* __restrict__ Wn, const float* __restrict__ bn,
                              const float* __restrict__ Wl, const float* __restrict__ bl) {
    int idx = blockIdx.x * blockDim.x + threadIdx.x;
    if (idx >= 3 * NHW_PAD * KP) return;
    int col = idx % KP;
    int rowm = idx / KP;
    int row = rowm % NHW_PAD;
    int mat = rowm / NHW_PAD;
    const float* W = (mat == 0) ? Wg : (mat == 1) ? Wn : Wl;
    const float* bs = (mat == 0) ? bg : (mat == 1) ? bn : bl;
    float v = 0.0f;
    if (row < EE) {
        if (col < EE)       v = W[(size_t)row * EE + col];
        else if (col == EE) v = bs[row];
    }
    g_B[idx] = __float2half(v);
}

// W_ih -> g_B fp16, (b_ih + b_hh) at col 825
__global__ void convWih_kernel(const float* __restrict__ W,
                               const float* __restrict__ b1, const float* __restrict__ b2) {
    int idx = blockIdx.x * blockDim.x + threadIdx.x;
    if (idx >= NIH_PAD * KP) return;
    int col = idx % KP, row = idx / KP;
    float v = 0.0f;
    if (row < NIH) {
        if (col < EE)       v = W[(size_t)row * EE + col];
        else if (col == EE) v = b1[row] + b2[row];
    }
    g_B[idx] = __float2half(v);
}

__global__ void convWhh_kernel(const float* __restrict__ W) {
    int idx = blockIdx.x * blockDim.x + threadIdx.x;
    if (idx >= 2 * G4P * HHP) return;
    int col = idx % HHP;
    int rowd = idx / HHP;
    int row = rowd % G4P;
    int d = rowd / G4P;
    float v = (row < G4 && col < HH) ? W[((size_t)d * G4 + row) * HH + col] : 0.0f;
    __nv_bfloat16 hi = __float2bfloat16(v);
    g_Whi[idx] = hi;
    g_Wlo[idx] = __float2bfloat16(v - __bfloat162float(hi));
}

// highway combine: raw G/N/L pre-biased; y -> fp16 out (ping-pong)
__global__ void combine_kernel(const float* __restrict__ rawG, const float* __restrict__ rawN,
                               const float* __restrict__ rawL,
                               __half* __restrict__ Aout) {
    int idx = blockIdx.x * blockDim.x + threadIdx.x;
    if (idx >= MROWS * KP) return;
    int col = idx % KP, row = idx / KP;
    float y;
    if (col < EE) {
        size_t r = (size_t)row * NHW_PAD + col;
        float gate = sigm(rawG[r]);
        float nl   = fmaxf(rawN[r], 0.0f);
        float ln   = rawL[r];
        y = gate * nl + (1.0f - gate) * ln;
    } else if (col == EE) y = 1.0f;
    else y = 0.0f;
    Aout[idx] = __float2half(y);
}

__global__ void finalize_kernel(float* __restrict__ out) {
    int idx = blockIdx.x * blockDim.x + threadIdx.x;
    if (idx >= OUT_BLK) return;
    const float* ctx_last = out + 4L * OUT_BLK + (long)(SS - 1) * OUT_BLK;
    float v = ctx_last[idx];
    out[idx] = v;
    out[OUT_BLK + idx] = v;
    out[2L * OUT_BLK + idx] = g_h[idx];
    out[3L * OUT_BLK + idx] = g_c[idx];
}

// ---------------------------------------------------------------------------
extern "C" void kernel_launch(void* const* d_in, const int* in_sizes, int n_in,
                              void* d_out, int out_size) {
    const float* x      = (const float*)d_in[0];
    const float* h0     = (const float*)d_in[1];
    const float* c0     = (const float*)d_in[2];
    const float* hw_Wg  = (const float*)d_in[3];
    const float* hw_bg  = (const float*)d_in[4];
    const float* hw_Wn  = (const float*)d_in[5];
    const float* hw_bn  = (const float*)d_in[6];
    const float* hw_Wl  = (const float*)d_in[7];
    const float* hw_bl  = (const float*)d_in[8];
    const float* W_ih   = (const float*)d_in[9];
    const float* W_hh   = (const float*)d_in[10];
    const float* b_ih   = (const float*)d_in[11];
    const float* b_hh   = (const float*)d_in[12];
    float* out = (float*)d_out;

    static bool attr_set = false;
    if (!attr_set) {
        cudaFuncSetAttribute(gemm_fp16_kernel,
                             cudaFuncAttributeMaxDynamicSharedMemorySize, 3 * STG);
        cudaFuncSetAttribute(step_fused_kernel,
                             cudaFuncAttributeMaxDynamicSharedMemorySize, 2 * SSTG);
        attr_set = true;
    }

    float *p_gates;
    __half *p_A1, *p_A2, *p_B;
    cudaGetSymbolAddress((void**)&p_gates, g_gates);
    cudaGetSymbolAddress((void**)&p_A1, g_A1);
    cudaGetSymbolAddress((void**)&p_A2, g_A2);
    cudaGetSymbolAddress((void**)&p_B, g_B);

    init_kernel<<<(2 * BB * HHP + 255) / 256, 256>>>(h0, c0);
    convWhh_kernel<<<(2 * G4P * HHP + 255) / 256, 256>>>(W_hh);
    convA_kernel<<<(MROWS * KP + 255) / 256, 256>>>(x);

    // Highway: 2 layers, 3 separate GEMMs + combine (pure fp16)
    float* raw[3] = { p_gates,
                      p_gates + (size_t)MROWS * NHW_PAD,
                      p_gates + 2 * (size_t)MROWS * NHW_PAD };
    dim3 gHW(MROWS / 128, NHW_PAD / 128);  // 256 x 7
    for (int l = 0; l < 2; l++) {
        convW3_kernel<<<(3 * NHW_PAD * KP + 255) / 256, 256>>>(
            hw_Wg + (size_t)l * EE * EE, hw_bg + l * EE,
            hw_Wn + (size_t)l * EE * EE, hw_bn + l * EE,
            hw_Wl + (size_t)l * EE * EE, hw_bl + l * EE);
        const __half* A = (l == 0) ? p_A1 : p_A2;
        for (int w = 0; w < 3; w++)
            gemm_fp16_kernel<<<gHW, 256, 3 * STG>>>(A,
                p_B + (size_t)w * NHW_PAD * KP, raw[w], NHW_PAD);
        combine_kernel<<<(MROWS * KP + 255) / 256, 256>>>(
            raw[0], raw[1], raw[2], (l == 0) ? p_A2 : p_A1);
    }

    // Input-gate precompute (bias folded via col 825)
    convWih_kernel<<<(NIH_PAD * KP + 255) / 256, 256>>>(W_ih, b_ih, b_hh);
    dim3 gGX(MROWS / 128, NIH_PAD / 128);  // 256 x 38
    gemm_fp16_kernel<<<gGX, 256, 3 * STG>>>(p_A1, p_B, p_gates, NIH_PAD);

    // Sequential recurrence: one fused kernel per step (R10 tile, K-chunk 64)
    dim3 gST(2, HH / 8, 2);  // 300 CTAs
    float* context = out + 4L * OUT_BLK;
    for (int t = 0; t < SS; t++) {
        step_fused_kernel<<<gST, 128, 2 * SSTG>>>(context, t);
    }

    finalize_kernel<<<(OUT_BLK + 255) / 256, 256>>>(out);
}

// round 16
// speedup vs baseline: 1.2315x; 1.0179x over previous
#include <cuda_runtime.h>
#include <cuda_bf16.h>
#include <cuda_fp16.h>
#include <cuda_pipeline.h>
#include <mma.h>
#include <math.h>
#include <stdint.h>

using namespace nvcuda;

// Problem constants
#define BB 128
#define SS 256
#define EE 825
#define KP 832            // E padded; col 825 = constant 1 (bias trick)
#define HH 600
#define HHP 640           // H padded to 10*64 (zero padding)
#define G4 2400
#define G4P 2432
#define MROWS 32768
#define CTX_STRIDE 1200
#define OUT_BLK 153600
#define NIH 4800
#define NIH_PAD 4864
#define NHW_PAD 896

// ---------------------------------------------------------------------------
// Scratch (device globals)
// ---------------------------------------------------------------------------
__device__ float g_gates[(size_t)MROWS * NIH_PAD];   // gates out; also highway raw scratch
__device__ __half g_A1[(size_t)MROWS * KP];          // activations fp16 (ping)
__device__ __half g_A2[(size_t)MROWS * KP];          // activations fp16 (pong)
__device__ __half g_B[(size_t)NIH_PAD * KP];         // weights fp16 (bias in col 825)
__device__ __nv_bfloat16 g_Whi[2 * G4P * HHP];       // recurrence weights split bf16
__device__ __nv_bfloat16 g_Wlo[2 * G4P * HHP];
__device__ __nv_bfloat16 g_hbf_hi[2][2 * BB * HHP];
__device__ __nv_bfloat16 g_hbf_lo[2][2 * BB * HHP];
__device__ float g_h[2 * BB * HH];
__device__ float g_c[2 * BB * HH];

__device__ __forceinline__ float sigm(float x) { return 1.0f / (1.0f + expf(-x)); }

// ---------------------------------------------------------------------------
// Big GEMM: C = A @ B^T, pure fp16, fp32 accum.
// 128x128 CTA tile, 8 warps (wm 0..3 x wn 0..1), warp 32x64.
// K-chunk 64: stage = 2 mats x 128 rows x 144B = 36864B; 3-stage ring.
// Commit-count kept aligned with empty commits (avoids last-stage race).
// ---------------------------------------------------------------------------
#define STG 36864

__global__ void __launch_bounds__(256) gemm_fp16_kernel(
        const __half* __restrict__ A, const __half* __restrict__ B,
        float* __restrict__ C, int ldc) {
    extern __shared__ char dsm[];
    const int tid = threadIdx.x;
    const int wid = tid >> 5;
    const int wm = wid >> 1;        // 0..3
    const int wn = wid & 1;         // 0..1
    const size_t m0 = (size_t)blockIdx.x * 128;
    const size_t n0 = (size_t)blockIdx.y * 128;
    const int NKB = KP / 64;        // 13

    const __half* gA = A + m0 * KP;
    const __half* gB = B + n0 * KP;

    wmma::fragment<wmma::accumulator, 16, 16, 16, float> acc[2][4];
    #pragma unroll
    for (int i = 0; i < 2; i++)
        #pragma unroll
        for (int j = 0; j < 4; j++)
            wmma::fill_fragment(acc[i][j], 0.0f);

    auto stage_fill = [&](int stg, int ko) {
        char* st = dsm + stg * STG;
        #pragma unroll
        for (int r = 0; r < 8; r++) {
            int idx = tid + r * 256;        // 0..2047
            int arr = idx >> 10;            // 0..1
            int rem = idx & 1023;
            int row = rem >> 3, seg = rem & 7;
            const __half* src = (arr ? gB : gA) + (size_t)row * KP + ko + seg * 8;
            __pipeline_memcpy_async(st + arr * 18432 + row * 144 + seg * 16, src, 16);
        }
        __pipeline_commit();
    };

    stage_fill(0, 0);
    stage_fill(1, 64);

    int stg = 0;
    for (int kb = 0; kb < NKB; kb++) {
        __pipeline_wait_prior(1);
        __syncthreads();
        if (kb + 2 < NKB)
            stage_fill((stg + 2) % 3, (kb + 2) * 64);
        else
            __pipeline_commit();        // keep commit count aligned

        char* st = dsm + stg * STG;
        typedef __half (*T72)[72];
        T72 sA = (T72)st;
        T72 sB = (T72)(st + 18432);

        #pragma unroll
        for (int ks = 0; ks < 4; ks++) {
            wmma::fragment<wmma::matrix_a, 16, 16, 16, __half, wmma::row_major> a[2];
            wmma::fragment<wmma::matrix_b, 16, 16, 16, __half, wmma::col_major> b[4];
            #pragma unroll
            for (int i = 0; i < 2; i++)
                wmma::load_matrix_sync(a[i], &sA[wm * 32 + i * 16][ks * 16], 72);
            #pragma unroll
            for (int j = 0; j < 4; j++)
                wmma::load_matrix_sync(b[j], &sB[wn * 64 + j * 16][ks * 16], 72);
            #pragma unroll
            for (int i = 0; i < 2; i++)
                #pragma unroll
                for (int j = 0; j < 4; j++)
                    wmma::mma_sync(acc[i][j], a[i], b[j], acc[i][j]);
        }
        stg = (stg + 1) % 3;
    }

    #pragma unroll
    for (int i = 0; i < 2; i++)
        #pragma unroll
        for (int j = 0; j < 4; j++)
            wmma::store_matrix_sync(&C[(m0 + wm * 32 + i * 16) * ldc + n0 + wn * 64 + j * 16],
                                    acc[i][j], ldc, wmma::mem_row_major);
}

// ---------------------------------------------------------------------------
// Fused recurrent step (R15 winner): 64x32 tile, K-chunk 64, 2-stage.
// grid (2, 75, 2) = 300 CTAs, 128 thr (4 warps).
// ---------------------------------------------------------------------------
#define SSTG 27648

__global__ void __launch_bounds__(128) step_fused_kernel(float* __restrict__ context, int t) {
    extern __shared__ char sm[];
    const int tid = threadIdx.x;
    const int wid = tid >> 5;             // 0..3 : 16-row slice
    const int mt = blockIdx.x;            // 0..1
    const int hh0 = blockIdx.y * 8;       // 0..592
    const int d = blockIdx.z;
    const int cur = t & 1, nxt = cur ^ 1;

    const __nv_bfloat16* Ahi = g_hbf_hi[cur] + (size_t)(d * BB + mt * 64) * HHP;
    const __nv_bfloat16* Alo = g_hbf_lo[cur] + (size_t)(d * BB + mt * 64) * HHP;
    const __nv_bfloat16* Whi = g_Whi + (size_t)d * G4P * HHP;
    const __nv_bfloat16* Wlo = g_Wlo + (size_t)d * G4P * HHP;

    wmma::fragment<wmma::accumulator, 16, 16, 16, float> acc[2];
    wmma::fill_fragment(acc[0], 0.0f);
    wmma::fill_fragment(acc[1], 0.0f);

    const int NKB = HHP / 64;             // 10

    auto stage_fill = [&](char* st, int ko) {
        #pragma unroll
        for (int r = 0; r < 8; r++) {
            int idx = tid + r * 128;
            int hl = idx >> 9;
            int rem = idx & 511;
            int row = rem >> 3, seg = rem & 7;
            const __nv_bfloat16* src = (hl ? Alo : Ahi) + (size_t)row * HHP + ko + seg * 8;
            __pipeline_memcpy_async(st + hl * 9216 + row * 144 + seg * 16, src, 16);
        }
        #pragma unroll
        for (int r = 0; r < 4; r++) {
            int idx = tid + r * 128;
            int hl = idx >> 8;
            int rem = idx & 255;
            int row = rem >> 3, seg = rem & 7;
            const __nv_bfloat16* src = (hl ? Wlo : Whi) +
                (size_t)((row >> 3) * HH + hh0 + (row & 7)) * HHP + ko + seg * 8;
            __pipeline_memcpy_async(st + 18432 + hl * 4608 + row * 144 + seg * 16, src, 16);
        }
        __pipeline_commit();
    };

    stage_fill(sm, 0);

    for (int kb = 0; kb < NKB; kb++) {
        __pipeline_wait_prior(0);
        __syncthreads();
        if (kb + 1 < NKB)
            stage_fill(sm + ((kb + 1) & 1) * SSTG, (kb + 1) * 64);

        char* st = sm + (kb & 1) * SSTG;
        typedef __nv_bfloat16 (*T72)[72];
        T72 sAh = (T72)st;
        T72 sAl = (T72)(st + 9216);
        T72 sBh = (T72)(st + 18432);
        T72 sBl = (T72)(st + 23040);

        #pragma unroll
        for (int ks = 0; ks < 4; ks++) {
            wmma::fragment<wmma::matrix_a, 16, 16, 16, __nv_bfloat16, wmma::row_major> ah, al;
            wmma::fragment<wmma::matrix_b, 16, 16, 16, __nv_bfloat16, wmma::col_major> bh[2], bl[2];
            wmma::load_matrix_sync(ah, &sAh[wid * 16][ks * 16], 72);
            wmma::load_matrix_sync(al, &sAl[wid * 16][ks * 16], 72);
            #pragma unroll
            for (int j = 0; j < 2; j++) {
                wmma::load_matrix_sync(bh[j], &sBh[j * 16][ks * 16], 72);
                wmma::load_matrix_sync(bl[j], &sBl[j * 16][ks * 16], 72);
            }
            #pragma unroll
            for (int j = 0; j < 2; j++) {
                wmma::mma_sync(acc[j], ah, bh[j], acc[j]);
                wmma::mma_sync(acc[j], ah, bl[j], acc[j]);
                wmma::mma_sync(acc[j], al, bh[j], acc[j]);
            }
        }
        __syncthreads();
    }

    // gates through smem (stage 0 alias; GEMM done): 64 x 32 f32 = 8KB
    float (*sg)[32] = (float(*)[32])sm;
    wmma::store_matrix_sync(&sg[wid * 16][0], acc[0], 32, wmma::mem_row_major);
    wmma::store_matrix_sync(&sg[wid * 16][16], acc[1], 32, wmma::mem_row_major);
    __syncthreads();

    // LSTM cell: 512 elements (64 rows x 8 hh)
    #pragma unroll
    for (int q = 0; q < 4; q++) {
        int e = tid + q * 128;
        int bl_ = e >> 3, hl = e & 7;
        int b = mt * 64 + bl_;
        int hh = hh0 + hl;
        size_t gx = ((size_t)b * SS + t) * NIH_PAD + d * G4;
        float gi = sg[bl_][hl]      + g_gates[gx + hh];
        float gf = sg[bl_][8 + hl]  + g_gates[gx + HH + hh];
        float gg = sg[bl_][16 + hl] + g_gates[gx + 2 * HH + hh];
        float go = sg[bl_][24 + hl] + g_gates[gx + 3 * HH + hh];
        size_t ci = (size_t)(d * BB + b) * HH + hh;
        float cold = g_c[ci];
        float cn = sigm(gf) * cold + sigm(gi) * tanhf(gg);
        float hn = sigm(go) * tanhf(cn);
        g_c[ci] = cn;
        g_h[ci] = hn;
        size_t hb = (size_t)(d * BB + b) * HHP + hh;
        __nv_bfloat16 hi = __float2bfloat16(hn);
        g_hbf_hi[nxt][hb] = hi;
        g_hbf_lo[nxt][hb] = __float2bfloat16(hn - __bfloat162float(hi));
        context[(size_t)t * OUT_BLK + (size_t)b * CTX_STRIDE + d * HH + hh] = hn;
    }
}

// ---------------------------------------------------------------------------
// Conversions / elementwise
// ---------------------------------------------------------------------------
__global__ void init_kernel(const float* __restrict__ h0, const float* __restrict__ c0) {
    int idx = blockIdx.x * blockDim.x + threadIdx.x;
    if (idx < 2 * BB * HH) { g_h[idx] = h0[idx]; g_c[idx] = c0[idx]; }
    if (idx < 2 * BB * HHP) {
        int hh = idx % HHP;
        int db = idx / HHP;
        float v = (hh < HH) ? h0[db * HH + hh] : 0.0f;
        __nv_bfloat16 hi = __float2bfloat16(v);
        __nv_bfloat16 lo = __float2bfloat16(v - __bfloat162float(hi));
        g_hbf_hi[0][idx] = hi; g_hbf_lo[0][idx] = lo;
        g_hbf_hi[1][idx] = hi; g_hbf_lo[1][idx] = lo;
    }
}

// x -> fp16, col 825 = 1.0 (bias column), cols > 825 = 0
__global__ void convA_kernel(const float* __restrict__ src) {
    int idx = blockIdx.x * blockDim.x + threadIdx.x;
    if (idx >= MROWS * KP) return;
    int col = idx % KP, row = idx / KP;
    float v;
    if (col < EE)       v = src[(size_t)row * EE + col];
    else if (col == EE) v = 1.0f;
    else                v = 0.0f;
    g_A1[idx] = __float2half(v);
}

// 3 highway weight mats (layer l) -> g_B fp16, bias at col 825
__global__ void convW3_kernel(const float* __restrict__ Wg, const float* __restrict__ bg,
                              const float* __restrict__ Wn, const float* __restrict__ bn,
                              const float* __restrict__ Wl, const float* __restrict__ bl) {
    int idx = blockIdx.x * blockDim.x + threadIdx.x;
    if (idx >= 3 * NHW_PAD * KP) return;
    int col = idx % KP;
    int rowm = idx / KP;
    int row = rowm % NHW_PAD;
    int mat = rowm / NHW_PAD;
    const float* W = (mat == 0) ? Wg : (mat == 1) ? Wn : Wl;
    const float* bs = (mat == 0) ? bg : (mat == 1) ? bn : bl;
    float v = 0.0f;
    if (row < EE) {
        if (col < EE)       v = W[(size_t)row * EE + col];
        else if (col == EE) v = bs[row];
    }
    g_B[idx] = __float2half(v);
}

// W_ih -> g_B fp16, (b_ih + b_hh) at col 825
__global__ void convWih_kernel(const float* __restrict__ W,
                               const float* __restrict__ b1, const float* __restrict__ b2) {
    int idx = blockIdx.x * blockDim.x + threadIdx.x;
    if (idx >= NIH_PAD * KP) return;
    int col = idx % KP, row = idx / KP;
    float v = 0.0f;
    if (row < NIH) {
        if (col < EE)       v = W[(size_t)row * EE + col];
        else if (col == EE) v = b1[row] + b2[row];
    }
    g_B[idx] = __float2half(v);
}

__global__ void convWhh_kernel(const float* __restrict__ W) {
    int idx = blockIdx.x * blockDim.x + threadIdx.x;
    if (idx >= 2 * G4P * HHP) return;
    int col = idx % HHP;
    int rowd = idx / HHP;
    int row = rowd % G4P;
    int d = rowd / G4P;
    float v = (row < G4 && col < HH) ? W[((size_t)d * G4 + row) * HH + col] : 0.0f;
    __nv_bfloat16 hi = __float2bfloat16(v);
    g_Whi[idx] = hi;
    g_Wlo[idx] = __float2bfloat16(v - __bfloat162float(hi));
}

// highway combine: raw G/N/L pre-biased; y -> fp16 out (ping-pong)
__global__ void combine_kernel(const float* __restrict__ rawG, const float* __restrict__ rawN,
                               const float* __restrict__ rawL,
                               __half* __restrict__ Aout) {
    int idx = blockIdx.x * blockDim.x + threadIdx.x;
    if (idx >= MROWS * KP) return;
    int col = idx % KP, row = idx / KP;
    float y;
    if (col < EE) {
        size_t r = (size_t)row * NHW_PAD + col;
        float gate = sigm(rawG[r]);
        float nl   = fmaxf(rawN[r], 0.0f);
        float ln   = rawL[r];
        y = gate * nl + (1.0f - gate) * ln;
    } else if (col == EE) y = 1.0f;
    else y = 0.0f;
    Aout[idx] = __float2half(y);
}

__global__ void finalize_kernel(float* __restrict__ out) {
    int idx = blockIdx.x * blockDim.x + threadIdx.x;
    if (idx >= OUT_BLK) return;
    const float* ctx_last = out + 4L * OUT_BLK + (long)(SS - 1) * OUT_BLK;
    float v = ctx_last[idx];
    out[idx] = v;
    out[OUT_BLK + idx] = v;
    out[2L * OUT_BLK + idx] = g_h[idx];
    out[3L * OUT_BLK + idx] = g_c[idx];
}

// ---------------------------------------------------------------------------
extern "C" void kernel_launch(void* const* d_in, const int* in_sizes, int n_in,
                              void* d_out, int out_size) {
    const float* x      = (const float*)d_in[0];
    const float* h0     = (const float*)d_in[1];
    const float* c0     = (const float*)d_in[2];
    const float* hw_Wg  = (const float*)d_in[3];
    const float* hw_bg  = (const float*)d_in[4];
    const float* hw_Wn  = (const float*)d_in[5];
    const float* hw_bn  = (const float*)d_in[6];
    const float* hw_Wl  = (const float*)d_in[7];
    const float* hw_bl  = (const float*)d_in[8];
    const float* W_ih   = (const float*)d_in[9];
    const float* W_hh   = (const float*)d_in[10];
    const float* b_ih   = (const float*)d_in[11];
    const float* b_hh   = (const float*)d_in[12];
    float* out = (float*)d_out;

    static bool attr_set = false;
    if (!attr_set) {
        cudaFuncSetAttribute(gemm_fp16_kernel,
                             cudaFuncAttributeMaxDynamicSharedMemorySize, 3 * STG);
        cudaFuncSetAttribute(step_fused_kernel,
                             cudaFuncAttributeMaxDynamicSharedMemorySize, 2 * SSTG);
        attr_set = true;
    }

    float *p_gates;
    __half *p_A1, *p_A2, *p_B;
    cudaGetSymbolAddress((void**)&p_gates, g_gates);
    cudaGetSymbolAddress((void**)&p_A1, g_A1);
    cudaGetSymbolAddress((void**)&p_A2, g_A2);
    cudaGetSymbolAddress((void**)&p_B, g_B);

    float* raw[3] = { p_gates,
                      p_gates + (size_t)MROWS * NHW_PAD,
                      p_gates + 2 * (size_t)MROWS * NHW_PAD };
    dim3 gHW(MROWS / 128, NHW_PAD / 128);  // 256 x 7
    dim3 gGX(MROWS / 128, NIH_PAD / 128);  // 256 x 38

    // Launch order arranged so the ncu capture position lands on a GEMM:
    // 0 init, 1 convWhh, 2 convW3(l0), 3 convA, 4 gemm, 5 gemm <- profiled
    init_kernel<<<(2 * BB * HHP + 255) / 256, 256>>>(h0, c0);
    convWhh_kernel<<<(2 * G4P * HHP + 255) / 256, 256>>>(W_hh);

    for (int l = 0; l < 2; l++) {
        convW3_kernel<<<(3 * NHW_PAD * KP + 255) / 256, 256>>>(
            hw_Wg + (size_t)l * EE * EE, hw_bg + l * EE,
            hw_Wn + (size_t)l * EE * EE, hw_bn + l * EE,
            hw_Wl + (size_t)l * EE * EE, hw_bl + l * EE);
        if (l == 0)
            convA_kernel<<<(MROWS * KP + 255) / 256, 256>>>(x);
        const __half* A = (l == 0) ? p_A1 : p_A2;
        for (int w = 0; w < 3; w++)
            gemm_fp16_kernel<<<gHW, 256, 3 * STG>>>(A,
                p_B + (size_t)w * NHW_PAD * KP, raw[w], NHW_PAD);
        combine_kernel<<<(MROWS * KP + 255) / 256, 256>>>(
            raw[0], raw[1], raw[2], (l == 0) ? p_A2 : p_A1);
    }

    // Input-gate precompute (bias folded via col 825)
    convWih_kernel<<<(NIH_PAD * KP + 255) / 256, 256>>>(W_ih, b_ih, b_hh);
    gemm_fp16_kernel<<<gGX, 256, 3 * STG>>>(p_A1, p_B, p_gates, NIH_PAD);

    // Sequential recurrence: one fused kernel per step (64x32 tile, K-chunk 64)
    dim3 gST(2, HH / 8, 2);  // 300 CTAs
    float* context = out + 4L * OUT_BLK;
    for (int t = 0; t < SS; t++) {
        step_fused_kernel<<<gST, 128, 2 * SSTG>>>(context, t);
    }

    finalize_kernel<<<(OUT_BLK + 255) / 256, 256>>>(out);
}